// round 5
// baseline (speedup 1.0000x reference)
#include <cuda_runtime.h>
#include <math.h>

#define Nn 10000
#define Ee 160000
#define Dd 512
#define Cc 64

// -------- scratch (__device__ globals) --------
__device__ float g_bufA[Nn * Dd];     // GEMM output / gather source
__device__ float g_bufB[Nn * Dd];     // aggregation output
__device__ int   g_deg[Nn];           // in-degree incl. self loop
__device__ float g_dis[Nn];           // 1/sqrt(deg)
__device__ int   g_src[Ee];
__device__ int   g_dst[Ee];
__device__ int   g_off[Nn + 1];       // CSR offsets (non-self incoming edges)
__device__ int   g_cur[Nn];           // fill cursors
__device__ int   g_eidx[Ee];          // CSR: source node per slot
__device__ float g_ew[Ee];            // CSR: edge weight dis[s]*dis[d]
__device__ int   g_is64;              // edge_index dtype flag

// -------- detect int32 vs int64 edge_index --------
// int64 node ids < 2^31 => every odd 32-bit word is 0. Sample 1024 pairs.
__global__ void k_detect(const int* __restrict__ ei32) {
    __shared__ int nz;
    if (threadIdx.x == 0) nz = 0;
    __syncthreads();
    for (int i = threadIdx.x; i < 1024; i += blockDim.x) {
        if (ei32[2 * i + 1] != 0) atomicAdd(&nz, 1);
    }
    __syncthreads();
    if (threadIdx.x == 0) g_is64 = (nz == 0) ? 1 : 0;
}

// -------- init: deg=1 (self loop), cursor=0 --------
__global__ void k_init() {
    int i = blockIdx.x * blockDim.x + threadIdx.x;
    if (i < Nn) { g_deg[i] = 1; g_cur[i] = 0; }
}

__device__ __forceinline__ int clampN(int v) {
    return min(max(v, 0), Nn - 1);
}

// -------- decode edges (either dtype) + count in-degree --------
__global__ void k_count(const void* __restrict__ ei) {
    int e = blockIdx.x * blockDim.x + threadIdx.x;
    if (e >= Ee) return;
    int s, d;
    if (g_is64) {
        s = (int)((const long long*)ei)[e];
        d = (int)((const long long*)ei)[Ee + e];
    } else {
        s = ((const int*)ei)[e];
        d = ((const int*)ei)[Ee + e];
    }
    s = clampN(s); d = clampN(d);
    g_src[e] = s;
    g_dst[e] = d;
    if (s != d) atomicAdd(&g_deg[d], 1);
}

__global__ void k_dis() {
    int i = blockIdx.x * blockDim.x + threadIdx.x;
    if (i < Nn) g_dis[i] = rsqrtf((float)g_deg[i]);
}

// -------- exclusive prefix scan of (deg-1): one 1024-thread block --------
__global__ void k_scan() {
    const int T = 1024, PER = (Nn + T - 1) / T;   // 10
    __shared__ int part[T];
    int t = threadIdx.x;
    int base = t * PER;
    int local[PER];
    int sum = 0;
#pragma unroll
    for (int i = 0; i < PER; i++) {
        int idx = base + i;
        int v = (idx < Nn) ? (g_deg[idx] - 1) : 0;
        local[i] = sum;
        sum += v;
    }
    part[t] = sum;
    __syncthreads();
    for (int off = 1; off < T; off <<= 1) {
        int v = (t >= off) ? part[t - off] : 0;
        __syncthreads();
        part[t] += v;
        __syncthreads();
    }
    int prev = (t > 0) ? part[t - 1] : 0;
#pragma unroll
    for (int i = 0; i < PER; i++) {
        int idx = base + i;
        if (idx < Nn) g_off[idx] = prev + local[i];
    }
    if (t == T - 1) g_off[Nn] = part[T - 1];
}

// -------- fill CSR edge lists --------
__global__ void k_fill() {
    int e = blockIdx.x * blockDim.x + threadIdx.x;
    if (e >= Ee) return;
    int s = g_src[e], d = g_dst[e];
    if (s == d) return;                       // dropped self-loops (weight 0)
    int pos = g_off[d] + atomicAdd(&g_cur[d], 1);
    if (pos >= 0 && pos < Ee) {
        g_eidx[pos] = s;
        g_ew[pos] = g_dis[s] * g_dis[d];
    }
}

// -------- tiled fp32 GEMM: bufA = In[M,512] @ W[512,512]; In = ext or bufB ----
__global__ void k_gemm(const float* __restrict__ Aext, const float* __restrict__ W,
                       int inSel, int M) {
    const int K = 512, NC = 512;
    const float* A = inSel ? g_bufB : Aext;
    __shared__ float As[64][16];
    __shared__ float Bs[16][64];
    int tid = threadIdx.x;              // 256 threads
    int tx = tid & 15;
    int ty = tid >> 4;
    int rowBase = blockIdx.y * 64;
    int colBase = blockIdx.x * 64;

    float acc[4][4];
#pragma unroll
    for (int i = 0; i < 4; i++)
#pragma unroll
        for (int j = 0; j < 4; j++) acc[i][j] = 0.0f;

    for (int k0 = 0; k0 < K; k0 += 16) {
        for (int i = tid; i < 64 * 16; i += 256) {
            int r = i >> 4, c = i & 15;
            int gr = rowBase + r;
            As[r][c] = (gr < M) ? A[(size_t)gr * K + k0 + c] : 0.0f;
        }
        for (int i = tid; i < 16 * 64; i += 256) {
            int r = i >> 6, c = i & 63;
            Bs[r][c] = W[(size_t)(k0 + r) * NC + colBase + c];
        }
        __syncthreads();
#pragma unroll
        for (int kk = 0; kk < 16; kk++) {
            float a[4], b[4];
#pragma unroll
            for (int i = 0; i < 4; i++) a[i] = As[ty * 4 + i][kk];
#pragma unroll
            for (int j = 0; j < 4; j++) b[j] = Bs[kk][tx * 4 + j];
#pragma unroll
            for (int i = 0; i < 4; i++)
#pragma unroll
                for (int j = 0; j < 4; j++) acc[i][j] += a[i] * b[j];
        }
        __syncthreads();
    }

#pragma unroll
    for (int i = 0; i < 4; i++) {
        int gr = rowBase + ty * 4 + i;
        if (gr < M) {
#pragma unroll
            for (int j = 0; j < 4; j++)
                g_bufA[(size_t)gr * NC + colBase + tx * 4 + j] = acc[i][j];
        }
    }
}

// -------- gather aggregation + bias (+relu), bufA -> bufB, no float atomics --
__global__ void k_aggr(const float* __restrict__ bias, int relu) {
    int n = blockIdx.x;
    int t = threadIdx.x;                               // 128 threads x float4
    float ds = g_dis[n];
    float w0 = ds * ds;                                // self-loop norm
    float4 v = ((const float4*)(g_bufA + (size_t)n * Dd))[t];
    float4 acc;
    acc.x = v.x * w0; acc.y = v.y * w0; acc.z = v.z * w0; acc.w = v.w * w0;

    int e0 = g_off[n], e1 = g_off[n + 1];
    for (int e = e0; e < e1; e++) {
        int s = g_eidx[e];
        float w = g_ew[e];
        float4 u = ((const float4*)(g_bufA + (size_t)s * Dd))[t];
        acc.x += u.x * w; acc.y += u.y * w; acc.z += u.z * w; acc.w += u.w * w;
    }

    float4 b = ((const float4*)bias)[t];
    acc.x += b.x; acc.y += b.y; acc.z += b.z; acc.w += b.w;
    if (relu) {
        acc.x = fmaxf(acc.x, 0.0f); acc.y = fmaxf(acc.y, 0.0f);
        acc.z = fmaxf(acc.z, 0.0f); acc.w = fmaxf(acc.w, 0.0f);
    }
    ((float4*)(g_bufB + (size_t)n * Dd))[t] = acc;
}

// -------- classifier + log_softmax, one node per block (64 threads) --------
__global__ void k_cls(const float* __restrict__ Wc, const float* __restrict__ bc,
                      float* __restrict__ logits, float* __restrict__ logp) {
    int n = blockIdx.x;
    __shared__ float xs[Dd];
    __shared__ float red[Cc];
    int t = threadIdx.x;
    for (int i = t; i < Dd; i += Cc) xs[i] = g_bufB[(size_t)n * Dd + i];
    __syncthreads();

    float acc = bc[t];
#pragma unroll 8
    for (int k = 0; k < Dd; k++) acc += xs[k] * Wc[k * Cc + t];

    logits[(size_t)n * Cc + t] = acc;

    red[t] = acc;
    __syncthreads();
    for (int s = 32; s > 0; s >>= 1) {
        if (t < s) red[t] = fmaxf(red[t], red[t + s]);
        __syncthreads();
    }
    float mx = red[0];
    __syncthreads();
    float ex = __expf(acc - mx);
    red[t] = ex;
    __syncthreads();
    for (int s = 32; s > 0; s >>= 1) {
        if (t < s) red[t] += red[t + s];
        __syncthreads();
    }
    float lse = mx + logf(red[0]);
    logp[(size_t)n * Cc + t] = acc - lse;
}

extern "C" void kernel_launch(void* const* d_in, const int* in_sizes, int n_in,
                              void* d_out, int out_size) {
    // ---- identify inputs by element count (robust to ordering) ----
    const float* x  = 0; const void* ei = 0;
    const float* W1 = 0; const float* b1 = 0;
    const float* W2 = 0; const float* b2 = 0;
    const float* Wc = 0; const float* bc = 0;
    for (int i = 0; i < n_in; i++) {
        int sz = in_sizes[i];
        if (sz == Nn * Dd)      { if (!x)  x  = (const float*)d_in[i]; }
        else if (sz == 2 * Ee)  { if (!ei) ei = d_in[i]; }
        else if (sz == Dd * Dd) { if (!W1) W1 = (const float*)d_in[i];
                                  else if (!W2) W2 = (const float*)d_in[i]; }
        else if (sz == Dd)      { if (!b1) b1 = (const float*)d_in[i];
                                  else if (!b2) b2 = (const float*)d_in[i]; }
        else if (sz == Dd * Cc) { if (!Wc) Wc = (const float*)d_in[i]; }
        else if (sz == Cc)      { if (!bc) bc = (const float*)d_in[i]; }
    }

    float* out    = (float*)d_out;
    float* logits = out;
    float* logp   = out + (out_size - Nn * Cc);

    // graph preprocessing (int atomics only; indices clamped)
    k_detect<<<1, 256>>>((const int*)ei);
    k_init<<<(Nn + 255) / 256, 256>>>();
    k_count<<<(Ee + 255) / 256, 256>>>(ei);
    k_dis<<<(Nn + 255) / 256, 256>>>();
    k_scan<<<1, 1024>>>();
    k_fill<<<(Ee + 255) / 256, 256>>>();

    dim3 gemmGrid(512 / 64, (Nn + 63) / 64);

    // ---- layer 1 ----
    k_gemm<<<gemmGrid, 256>>>(x, W1, 0, Nn);
    k_aggr<<<Nn, Dd / 4>>>(b1, 1);

    // ---- layer 2 ----
    k_gemm<<<gemmGrid, 256>>>(x /*unused*/, W2, 1, Nn);
    k_aggr<<<Nn, Dd / 4>>>(b2, 0);

    // ---- classifier + log_softmax ----
    k_cls<<<Nn, Cc>>>(Wc, bc, logits, logp);
}

// round 7
// speedup vs baseline: 1.8161x; 1.8161x over previous
#include <cuda_runtime.h>
#include <cuda_bf16.h>
#include <math.h>
#include <stdint.h>

#define Nn 10000
#define Ee 160000
#define Dd 512
#define Cc 64

#define KC 32                 // K chunk
#define APAD 8                // smem row pad (stride 40 bf16 = 80B, 16B-aligned)

// -------- scratch --------
__device__ float g_bufA[Nn * Dd];
__device__ float g_bufB[Nn * Dd];
__device__ int   g_deg[Nn];
__device__ float g_dis[Nn];
__device__ int   g_src[Ee];
__device__ int   g_dst[Ee];
__device__ int   g_off[Nn + 1];
__device__ int   g_cur[Nn];
__device__ int   g_eidx[Ee];
__device__ float g_ew[Ee];
__device__ int   g_is64;
__device__ __align__(16) __nv_bfloat16 g_Ahi[Nn * Dd];
__device__ __align__(16) __nv_bfloat16 g_Alo[Nn * Dd];
__device__ __align__(16) __nv_bfloat16 g_WThi[Dd * Dd];   // [n][k]
__device__ __align__(16) __nv_bfloat16 g_WTlo[Dd * Dd];

// ======== graph preprocessing ========
__global__ void k_detect(const int* __restrict__ ei32) {
    __shared__ int nz;
    if (threadIdx.x == 0) nz = 0;
    __syncthreads();
    for (int i = threadIdx.x; i < 1024; i += blockDim.x)
        if (ei32[2 * i + 1] != 0) atomicAdd(&nz, 1);
    __syncthreads();
    if (threadIdx.x == 0) g_is64 = (nz == 0) ? 1 : 0;
}

__global__ void k_init() {
    int i = blockIdx.x * blockDim.x + threadIdx.x;
    if (i < Nn) { g_deg[i] = 1; g_cur[i] = 0; }
}

static __device__ __forceinline__ int clampN(int v) { return min(max(v, 0), Nn - 1); }

__global__ void k_count(const void* __restrict__ ei) {
    int e = blockIdx.x * blockDim.x + threadIdx.x;
    if (e >= Ee) return;
    int s, d;
    if (g_is64) {
        s = (int)((const long long*)ei)[e];
        d = (int)((const long long*)ei)[Ee + e];
    } else {
        s = ((const int*)ei)[e];
        d = ((const int*)ei)[Ee + e];
    }
    s = clampN(s); d = clampN(d);
    g_src[e] = s; g_dst[e] = d;
    if (s != d) atomicAdd(&g_deg[d], 1);
}

__global__ void k_dis() {
    int i = blockIdx.x * blockDim.x + threadIdx.x;
    if (i < Nn) g_dis[i] = rsqrtf((float)g_deg[i]);
}

__global__ void k_scan() {
    const int T = 1024, PER = (Nn + T - 1) / T;
    __shared__ int part[T];
    int t = threadIdx.x, base = t * PER, local[PER], sum = 0;
#pragma unroll
    for (int i = 0; i < PER; i++) {
        int idx = base + i;
        int v = (idx < Nn) ? (g_deg[idx] - 1) : 0;
        local[i] = sum; sum += v;
    }
    part[t] = sum;
    __syncthreads();
    for (int off = 1; off < T; off <<= 1) {
        int v = (t >= off) ? part[t - off] : 0;
        __syncthreads();
        part[t] += v;
        __syncthreads();
    }
    int prev = (t > 0) ? part[t - 1] : 0;
#pragma unroll
    for (int i = 0; i < PER; i++) {
        int idx = base + i;
        if (idx < Nn) g_off[idx] = prev + local[i];
    }
    if (t == T - 1) g_off[Nn] = part[T - 1];
}

__global__ void k_fill() {
    int e = blockIdx.x * blockDim.x + threadIdx.x;
    if (e >= Ee) return;
    int s = g_src[e], d = g_dst[e];
    if (s == d) return;
    int pos = g_off[d] + atomicAdd(&g_cur[d], 1);
    if (pos >= 0 && pos < Ee) { g_eidx[pos] = s; g_ew[pos] = g_dis[s] * g_dis[d]; }
}

// ======== bf16 hi/lo splits ========
__global__ void k_splitW(const float* __restrict__ W) {     // W[k][n] -> WT[n][k]
    int idx = blockIdx.x * blockDim.x + threadIdx.x;
    if (idx >= Dd * Dd) return;
    int k = idx >> 9, n = idx & 511;
    float v = W[idx];
    __nv_bfloat16 h = __float2bfloat16(v);
    float r = v - __bfloat162float(h);
    g_WThi[n * Dd + k] = h;
    g_WTlo[n * Dd + k] = __float2bfloat16(r);
}

__global__ void k_splitA(const float* __restrict__ ext, int sel) {
    int idx = blockIdx.x * blockDim.x + threadIdx.x;
    if (idx >= Nn * Dd) return;
    float v = sel ? g_bufB[idx] : ext[idx];
    __nv_bfloat16 h = __float2bfloat16(v);
    float r = v - __bfloat162float(h);
    g_Ahi[idx] = h;
    g_Alo[idx] = __float2bfloat16(r);
}

// ======== bf16 mma.sync GEMM (3-pass hi/lo): bufA = A @ W ========
// CTA tile 128(m) x 128(n); 8 warps as 2(m) x 4(n); warp tile 64x32.
// mma.m16n8k16 row.col: B col-major == WT[n][k] (k contiguous).
static __device__ __forceinline__ void mma16816(
    float& c0, float& c1, float& c2, float& c3,
    uint32_t a0, uint32_t a1, uint32_t a2, uint32_t a3,
    uint32_t b0, uint32_t b1) {
    asm volatile(
        "mma.sync.aligned.m16n8k16.row.col.f32.bf16.bf16.f32 "
        "{%0,%1,%2,%3}, {%4,%5,%6,%7}, {%8,%9}, {%0,%1,%2,%3};"
        : "+f"(c0), "+f"(c1), "+f"(c2), "+f"(c3)
        : "r"(a0), "r"(a1), "r"(a2), "r"(a3), "r"(b0), "r"(b1));
}

__global__ void __launch_bounds__(256) k_gemm_mma() {
    __shared__ __align__(16) __nv_bfloat16 Asm[128][KC + APAD];
    __shared__ __align__(16) __nv_bfloat16 Bsm[128][KC + APAD];

    int tid = threadIdx.x;
    int m0 = blockIdx.y * 128;
    int n0 = blockIdx.x * 128;
    int wid = tid >> 5, lane = tid & 31;
    int warp_m = wid >> 2, warp_n = wid & 3;      // 2 x 4
    int q = lane >> 2, tq = lane & 3;             // quad row, pair col

    float c[4][4][4];
#pragma unroll
    for (int mi = 0; mi < 4; mi++)
#pragma unroll
        for (int ni = 0; ni < 4; ni++)
#pragma unroll
            for (int j = 0; j < 4; j++) c[mi][ni][j] = 0.0f;

    for (int pass = 0; pass < 3; pass++) {
        const __nv_bfloat16* Asrc = (pass == 1) ? g_Alo : g_Ahi;
        const __nv_bfloat16* Bsrc = (pass == 2) ? g_WTlo : g_WThi;
        for (int kc = 0; kc < Dd; kc += KC) {
            // stage A chunk: 128 rows x 32 bf16 (4 uint4 per row)
#pragma unroll
            for (int i = tid; i < 512; i += 256) {
                int r = i >> 2, seg = i & 3;
                int gm = m0 + r;
                uint4 v = make_uint4(0, 0, 0, 0);
                if (gm < Nn)
                    v = *(const uint4*)(Asrc + (size_t)gm * Dd + kc + seg * 8);
                *(uint4*)&Asm[r][seg * 8] = v;
            }
            // stage B chunk: WT rows n0..n0+127, 32 bf16 each
#pragma unroll
            for (int i = tid; i < 512; i += 256) {
                int r = i >> 2, seg = i & 3;
                uint4 v = *(const uint4*)(Bsrc + (size_t)(n0 + r) * Dd + kc + seg * 8);
                *(uint4*)&Bsm[r][seg * 8] = v;
            }
            __syncthreads();

#pragma unroll
            for (int ks = 0; ks < KC; ks += 16) {
                uint32_t bf[4][2];
#pragma unroll
                for (int ni = 0; ni < 4; ni++) {
                    int n = warp_n * 32 + ni * 8 + q;
                    bf[ni][0] = *(const uint32_t*)&Bsm[n][ks + 2 * tq];
                    bf[ni][1] = *(const uint32_t*)&Bsm[n][ks + 2 * tq + 8];
                }
#pragma unroll
                for (int mi = 0; mi < 4; mi++) {
                    int r = warp_m * 64 + mi * 16 + q;
                    uint32_t a0 = *(const uint32_t*)&Asm[r][ks + 2 * tq];
                    uint32_t a1 = *(const uint32_t*)&Asm[r + 8][ks + 2 * tq];
                    uint32_t a2 = *(const uint32_t*)&Asm[r][ks + 2 * tq + 8];
                    uint32_t a3 = *(const uint32_t*)&Asm[r + 8][ks + 2 * tq + 8];
#pragma unroll
                    for (int ni = 0; ni < 4; ni++)
                        mma16816(c[mi][ni][0], c[mi][ni][1], c[mi][ni][2], c[mi][ni][3],
                                 a0, a1, a2, a3, bf[ni][0], bf[ni][1]);
                }
            }
            __syncthreads();
        }
    }

    // write out: C fragment rows q/q+8, cols 2tq/2tq+1
#pragma unroll
    for (int mi = 0; mi < 4; mi++) {
#pragma unroll
        for (int ni = 0; ni < 4; ni++) {
            int m = m0 + warp_m * 64 + mi * 16 + q;
            int n = n0 + warp_n * 32 + ni * 8 + 2 * tq;
            if (m < Nn)
                *(float2*)(g_bufA + (size_t)m * Dd + n) =
                    make_float2(c[mi][ni][0], c[mi][ni][1]);
            if (m + 8 < Nn)
                *(float2*)(g_bufA + (size_t)(m + 8) * Dd + n) =
                    make_float2(c[mi][ni][2], c[mi][ni][3]);
        }
    }
}

// ======== gather aggregation + bias (+relu), bufA -> bufB ========
__global__ void k_aggr(const float* __restrict__ bias, int relu) {
    int n = blockIdx.x;
    int t = threadIdx.x;
    float ds = g_dis[n];
    float w0 = ds * ds;
    float4 v = ((const float4*)(g_bufA + (size_t)n * Dd))[t];
    float4 acc;
    acc.x = v.x * w0; acc.y = v.y * w0; acc.z = v.z * w0; acc.w = v.w * w0;
    int e0 = g_off[n], e1 = g_off[n + 1];
    for (int e = e0; e < e1; e++) {
        int s = g_eidx[e];
        float w = g_ew[e];
        float4 u = ((const float4*)(g_bufA + (size_t)s * Dd))[t];
        acc.x += u.x * w; acc.y += u.y * w; acc.z += u.z * w; acc.w += u.w * w;
    }
    float4 b = ((const float4*)bias)[t];
    acc.x += b.x; acc.y += b.y; acc.z += b.z; acc.w += b.w;
    if (relu) {
        acc.x = fmaxf(acc.x, 0.0f); acc.y = fmaxf(acc.y, 0.0f);
        acc.z = fmaxf(acc.z, 0.0f); acc.w = fmaxf(acc.w, 0.0f);
    }
    ((float4*)(g_bufB + (size_t)n * Dd))[t] = acc;
}

// ======== classifier + log_softmax: 16 nodes/block, 256 threads ========
__global__ void k_cls(const float* __restrict__ Wc, const float* __restrict__ bc,
                      float* __restrict__ logits, float* __restrict__ logp) {
    __shared__ float xs[16][Dd];
    int t = threadIdx.x;
    int n0 = blockIdx.x * 16;
    int c4 = (t & 15) * 4;
    int g  = t >> 4;

#pragma unroll
    for (int i = 0; i < 8; i++) {
        int slot = t + i * 256;
        int node = slot >> 7, qq = slot & 127;
        ((float4*)xs[node])[qq] = ((const float4*)(g_bufB + (size_t)(n0 + node) * Dd))[qq];
    }
    __syncthreads();

    float a0 = 0.f, a1 = 0.f, a2 = 0.f, a3 = 0.f;
    for (int k = 0; k < Dd; k += 4) {
        float4 xv = *(const float4*)&xs[g][k];
        float4 w0 = *(const float4*)(Wc + (size_t)k * Cc + c4);
        float4 w1 = *(const float4*)(Wc + (size_t)(k + 1) * Cc + c4);
        float4 w2 = *(const float4*)(Wc + (size_t)(k + 2) * Cc + c4);
        float4 w3 = *(const float4*)(Wc + (size_t)(k + 3) * Cc + c4);
        a0 += xv.x * w0.x + xv.y * w1.x + xv.z * w2.x + xv.w * w3.x;
        a1 += xv.x * w0.y + xv.y * w1.y + xv.z * w2.y + xv.w * w3.y;
        a2 += xv.x * w0.z + xv.y * w1.z + xv.z * w2.z + xv.w * w3.z;
        a3 += xv.x * w0.w + xv.y * w1.w + xv.z * w2.w + xv.w * w3.w;
    }
    float4 bv = *(const float4*)(bc + c4);
    a0 += bv.x; a1 += bv.y; a2 += bv.z; a3 += bv.w;

    int n = n0 + g;
    *(float4*)(logits + (size_t)n * Cc + c4) = make_float4(a0, a1, a2, a3);

    float mx = fmaxf(fmaxf(a0, a1), fmaxf(a2, a3));
#pragma unroll
    for (int m = 8; m > 0; m >>= 1)
        mx = fmaxf(mx, __shfl_xor_sync(0xffffffffu, mx, m, 16));
    float es = __expf(a0 - mx) + __expf(a1 - mx) + __expf(a2 - mx) + __expf(a3 - mx);
#pragma unroll
    for (int m = 8; m > 0; m >>= 1)
        es += __shfl_xor_sync(0xffffffffu, es, m, 16);
    float lse = mx + logf(es);
    *(float4*)(logp + (size_t)n * Cc + c4) =
        make_float4(a0 - lse, a1 - lse, a2 - lse, a3 - lse);
}

extern "C" void kernel_launch(void* const* d_in, const int* in_sizes, int n_in,
                              void* d_out, int out_size) {
    const float* x  = 0; const void* ei = 0;
    const float* W1 = 0; const float* b1 = 0;
    const float* W2 = 0; const float* b2 = 0;
    const float* Wc = 0; const float* bc = 0;
    for (int i = 0; i < n_in; i++) {
        int sz = in_sizes[i];
        if (sz == Nn * Dd)      { if (!x)  x  = (const float*)d_in[i]; }
        else if (sz == 2 * Ee)  { if (!ei) ei = d_in[i]; }
        else if (sz == Dd * Dd) { if (!W1) W1 = (const float*)d_in[i];
                                  else if (!W2) W2 = (const float*)d_in[i]; }
        else if (sz == Dd)      { if (!b1) b1 = (const float*)d_in[i];
                                  else if (!b2) b2 = (const float*)d_in[i]; }
        else if (sz == Dd * Cc) { if (!Wc) Wc = (const float*)d_in[i]; }
        else if (sz == Cc)      { if (!bc) bc = (const float*)d_in[i]; }
    }

    float* out    = (float*)d_out;
    float* logits = out;
    float* logp   = out + (out_size - Nn * Cc);

    k_detect<<<1, 256>>>((const int*)ei);
    k_init<<<(Nn + 255) / 256, 256>>>();
    k_count<<<(Ee + 255) / 256, 256>>>(ei);
    k_dis<<<(Nn + 255) / 256, 256>>>();
    k_scan<<<1, 1024>>>();
    k_fill<<<(Ee + 255) / 256, 256>>>();

    dim3 gemmGrid(Dd / 128, (Nn + 127) / 128);   // 4 x 79

    // ---- layer 1 ----
    k_splitW<<<(Dd * Dd + 255) / 256, 256>>>(W1);
    k_splitA<<<(Nn * Dd + 255) / 256, 256>>>(x, 0);
    k_gemm_mma<<<gemmGrid, 256>>>();
    k_aggr<<<Nn, Dd / 4>>>(b1, 1);

    // ---- layer 2 ----
    k_splitW<<<(Dd * Dd + 255) / 256, 256>>>(W2);
    k_splitA<<<(Nn * Dd + 255) / 256, 256>>>(x, 1);
    k_gemm_mma<<<gemmGrid, 256>>>();
    k_aggr<<<Nn, Dd / 4>>>(b2, 0);

    // ---- classifier + log_softmax ----
    k_cls<<<Nn / 16, 256>>>(Wc, bc, logits, logp);
}

// round 8
// speedup vs baseline: 2.2065x; 1.2150x over previous
#include <cuda_runtime.h>
#include <cuda_bf16.h>
#include <math.h>
#include <stdint.h>

#define Nn 10000
#define Ee 160000
#define Dd 512
#define Cc 64

#define KC 32                    // K chunk
#define SROW 40                  // smem row stride in bf16 (80B)
#define TILE_B (128 * SROW * 2)  // 10240 B per tile
#define STAGE_B (4 * TILE_B)     // Ahi,Alo,Bhi,Blo = 40960 B
#define NKC (Dd / KC)            // 16

// -------- scratch --------
__device__ float g_bufA[Nn * Dd];
__device__ float g_bufB[Nn * Dd];
__device__ int   g_deg[Nn];
__device__ float g_dis[Nn];
__device__ int   g_src[Ee];
__device__ int   g_dst[Ee];
__device__ int   g_off[Nn + 1];
__device__ int   g_cur[Nn];
__device__ int   g_eidx[Ee];
__device__ float g_ew[Ee];
__device__ int   g_is64;
__device__ __align__(16) __nv_bfloat16 g_Ahi[Nn * Dd];
__device__ __align__(16) __nv_bfloat16 g_Alo[Nn * Dd];
__device__ __align__(16) __nv_bfloat16 g_W1hi[Dd * Dd];   // [n][k]
__device__ __align__(16) __nv_bfloat16 g_W1lo[Dd * Dd];
__device__ __align__(16) __nv_bfloat16 g_W2hi[Dd * Dd];
__device__ __align__(16) __nv_bfloat16 g_W2lo[Dd * Dd];

#define CP_ASYNC16(smem, gmem, sz) \
    asm volatile("cp.async.cg.shared.global [%0], [%1], 16, %2;" \
                 :: "r"(smem), "l"(gmem), "r"(sz))
#define CP_COMMIT() asm volatile("cp.async.commit_group;" ::: "memory")
#define CP_WAIT(n)  asm volatile("cp.async.wait_group %0;" :: "n"(n) : "memory")

static __device__ __forceinline__ uint32_t smem_u32(const void* p) {
    uint32_t a;
    asm("{ .reg .u64 t; cvta.to.shared.u64 t, %1; cvt.u32.u64 %0, t; }"
        : "=r"(a) : "l"(p));
    return a;
}

// ======== graph preprocessing ========
__global__ void k_detect_init(const int* __restrict__ ei32) {
    int i = blockIdx.x * blockDim.x + threadIdx.x;
    if (i < Nn) { g_deg[i] = 1; g_cur[i] = 0; }
    if (blockIdx.x == 0) {
        __shared__ int nz;
        if (threadIdx.x == 0) nz = 0;
        __syncthreads();
        for (int j = threadIdx.x; j < 1024; j += blockDim.x)
            if (ei32[2 * j + 1] != 0) atomicAdd(&nz, 1);
        __syncthreads();
        if (threadIdx.x == 0) g_is64 = (nz == 0) ? 1 : 0;
    }
}

static __device__ __forceinline__ int clampN(int v) { return min(max(v, 0), Nn - 1); }

__global__ void k_count(const void* __restrict__ ei) {
    int e = blockIdx.x * blockDim.x + threadIdx.x;
    if (e >= Ee) return;
    int s, d;
    if (g_is64) {
        s = (int)((const long long*)ei)[e];
        d = (int)((const long long*)ei)[Ee + e];
    } else {
        s = ((const int*)ei)[e];
        d = ((const int*)ei)[Ee + e];
    }
    s = clampN(s); d = clampN(d);
    g_src[e] = s; g_dst[e] = d;
    if (s != d) atomicAdd(&g_deg[d], 1);
}

// scan of (deg-1) + dis computation, single 1024-thread block
__global__ void k_scan() {
    const int T = 1024, PER = (Nn + T - 1) / T;
    __shared__ int part[T];
    int t = threadIdx.x, base = t * PER, local[PER], sum = 0;
#pragma unroll
    for (int i = 0; i < PER; i++) {
        int idx = base + i;
        int dg = (idx < Nn) ? g_deg[idx] : 1;
        if (idx < Nn) g_dis[idx] = rsqrtf((float)dg);
        local[i] = sum; sum += dg - 1;
    }
    part[t] = sum;
    __syncthreads();
    for (int off = 1; off < T; off <<= 1) {
        int v = (t >= off) ? part[t - off] : 0;
        __syncthreads();
        part[t] += v;
        __syncthreads();
    }
    int prev = (t > 0) ? part[t - 1] : 0;
#pragma unroll
    for (int i = 0; i < PER; i++) {
        int idx = base + i;
        if (idx < Nn) g_off[idx] = prev + local[i];
    }
    if (t == T - 1) g_off[Nn] = part[T - 1];
}

__global__ void k_fill() {
    int e = blockIdx.x * blockDim.x + threadIdx.x;
    if (e >= Ee) return;
    int s = g_src[e], d = g_dst[e];
    if (s == d) return;
    int pos = g_off[d] + atomicAdd(&g_cur[d], 1);
    if (pos >= 0 && pos < Ee) { g_eidx[pos] = s; g_ew[pos] = g_dis[s] * g_dis[d]; }
}

// ======== bf16 hi/lo splits ========
__global__ void k_splitW(const float* __restrict__ W1, const float* __restrict__ W2) {
    int idx = blockIdx.x * blockDim.x + threadIdx.x;
    if (idx >= 2 * Dd * Dd) return;
    int layer = idx >= Dd * Dd;
    int li = layer ? idx - Dd * Dd : idx;
    int k = li >> 9, n = li & 511;
    float v = layer ? W2[li] : W1[li];
    __nv_bfloat16 h = __float2bfloat16(v);
    float r = v - __bfloat162float(h);
    if (layer) { g_W2hi[n * Dd + k] = h; g_W2lo[n * Dd + k] = __float2bfloat16(r); }
    else       { g_W1hi[n * Dd + k] = h; g_W1lo[n * Dd + k] = __float2bfloat16(r); }
}

__global__ void k_splitA(const float* __restrict__ x) {
    int idx = blockIdx.x * blockDim.x + threadIdx.x;
    if (idx >= Nn * Dd) return;
    float v = x[idx];
    __nv_bfloat16 h = __float2bfloat16(v);
    float r = v - __bfloat162float(h);
    g_Ahi[idx] = h;
    g_Alo[idx] = __float2bfloat16(r);
}

// ======== fused 3-pass bf16 mma GEMM with cp.async double buffer ========
// bufA[m][n] = A[m][:] @ W[:, n];  A from g_Ahi/g_Alo, W from layer's hi/lo.
static __device__ __forceinline__ void mma16816(
    float& c0, float& c1, float& c2, float& c3,
    uint32_t a0, uint32_t a1, uint32_t a2, uint32_t a3,
    uint32_t b0, uint32_t b1) {
    asm volatile(
        "mma.sync.aligned.m16n8k16.row.col.f32.bf16.bf16.f32 "
        "{%0,%1,%2,%3}, {%4,%5,%6,%7}, {%8,%9}, {%0,%1,%2,%3};"
        : "+f"(c0), "+f"(c1), "+f"(c2), "+f"(c3)
        : "r"(a0), "r"(a1), "r"(a2), "r"(a3), "r"(b0), "r"(b1));
}

extern __shared__ char dynsm[];

__global__ void __launch_bounds__(256) k_gemm_mma(int layer) {
    const __nv_bfloat16* Bhi = layer ? g_W2hi : g_W1hi;
    const __nv_bfloat16* Blo = layer ? g_W2lo : g_W1lo;

    int tid = threadIdx.x;
    int m0 = blockIdx.y * 128;
    int n0 = blockIdx.x * 128;
    int wid = tid >> 5, lane = tid & 31;
    int warp_m = wid >> 2, warp_n = wid & 3;      // 2 x 4
    int q = lane >> 2, tq = lane & 3;

    float c[4][4][4];
#pragma unroll
    for (int mi = 0; mi < 4; mi++)
#pragma unroll
        for (int ni = 0; ni < 4; ni++)
#pragma unroll
            for (int j = 0; j < 4; j++) c[mi][ni][j] = 0.0f;

    // issue cp.async for one k-chunk into stage buf
    auto issue = [&](int buf, int kc) {
        char* base = dynsm + buf * STAGE_B;
#pragma unroll
        for (int j = 0; j < 8; j++) {
            int slot = tid + j * 256;             // 0..2047
            int tile = slot >> 9;                 // 0:Ahi 1:Alo 2:Bhi 3:Blo
            int w = slot & 511;
            int r = w >> 2, seg = w & 3;
            const __nv_bfloat16* src;
            int valid = 16;
            if (tile < 2) {
                int gm = m0 + r;
                if (gm >= Nn) { gm = 0; valid = 0; }
                src = (tile == 0 ? g_Ahi : g_Alo) + (size_t)gm * Dd + kc * KC + seg * 8;
            } else {
                src = (tile == 2 ? Bhi : Blo) + (size_t)(n0 + r) * Dd + kc * KC + seg * 8;
            }
            uint32_t dst = smem_u32(base + tile * TILE_B + (r * SROW + seg * 8) * 2);
            CP_ASYNC16(dst, src, valid);
        }
        CP_COMMIT();
    };

    issue(0, 0);

    for (int kc = 0; kc < NKC; kc++) {
        if (kc + 1 < NKC) {
            issue((kc + 1) & 1, kc + 1);
            CP_WAIT(1);
        } else {
            CP_WAIT(0);
        }
        __syncthreads();

        char* base = dynsm + (kc & 1) * STAGE_B;
        const char* pAhi = base;
        const char* pAlo = base + TILE_B;
        const char* pBhi = base + 2 * TILE_B;
        const char* pBlo = base + 3 * TILE_B;

#pragma unroll
        for (int ks = 0; ks < KC; ks += 16) {
            uint32_t bh[4][2], bl[4][2];
#pragma unroll
            for (int ni = 0; ni < 4; ni++) {
                int n = warp_n * 32 + ni * 8 + q;
                int o0 = (n * SROW + ks + 2 * tq) * 2;
                int o1 = (n * SROW + ks + 2 * tq + 8) * 2;
                bh[ni][0] = *(const uint32_t*)(pBhi + o0);
                bh[ni][1] = *(const uint32_t*)(pBhi + o1);
                bl[ni][0] = *(const uint32_t*)(pBlo + o0);
                bl[ni][1] = *(const uint32_t*)(pBlo + o1);
            }
#pragma unroll
            for (int mi = 0; mi < 4; mi++) {
                int r = warp_m * 64 + mi * 16 + q;
                int o0 = (r * SROW + ks + 2 * tq) * 2;
                int o1 = ((r + 8) * SROW + ks + 2 * tq) * 2;
                int o2 = (r * SROW + ks + 2 * tq + 8) * 2;
                int o3 = ((r + 8) * SROW + ks + 2 * tq + 8) * 2;
                uint32_t ah0 = *(const uint32_t*)(pAhi + o0);
                uint32_t ah1 = *(const uint32_t*)(pAhi + o1);
                uint32_t ah2 = *(const uint32_t*)(pAhi + o2);
                uint32_t ah3 = *(const uint32_t*)(pAhi + o3);
                uint32_t al0 = *(const uint32_t*)(pAlo + o0);
                uint32_t al1 = *(const uint32_t*)(pAlo + o1);
                uint32_t al2 = *(const uint32_t*)(pAlo + o2);
                uint32_t al3 = *(const uint32_t*)(pAlo + o3);
#pragma unroll
                for (int ni = 0; ni < 4; ni++) {
                    mma16816(c[mi][ni][0], c[mi][ni][1], c[mi][ni][2], c[mi][ni][3],
                             ah0, ah1, ah2, ah3, bh[ni][0], bh[ni][1]);
                    mma16816(c[mi][ni][0], c[mi][ni][1], c[mi][ni][2], c[mi][ni][3],
                             al0, al1, al2, al3, bh[ni][0], bh[ni][1]);
                    mma16816(c[mi][ni][0], c[mi][ni][1], c[mi][ni][2], c[mi][ni][3],
                             ah0, ah1, ah2, ah3, bl[ni][0], bl[ni][1]);
                }
            }
        }
        __syncthreads();
    }

#pragma unroll
    for (int mi = 0; mi < 4; mi++) {
#pragma unroll
        for (int ni = 0; ni < 4; ni++) {
            int m = m0 + warp_m * 64 + mi * 16 + q;
            int n = n0 + warp_n * 32 + ni * 8 + 2 * tq;
            if (m < Nn)
                *(float2*)(g_bufA + (size_t)m * Dd + n) =
                    make_float2(c[mi][ni][0], c[mi][ni][1]);
            if (m + 8 < Nn)
                *(float2*)(g_bufA + (size_t)(m + 8) * Dd + n) =
                    make_float2(c[mi][ni][2], c[mi][ni][3]);
        }
    }
}

// ======== gather aggregation + bias (+relu); output fp32 bufB or bf16 split ==
__global__ void k_aggr(const float* __restrict__ bias, int relu, int writeSplit) {
    int n = blockIdx.x;
    int t = threadIdx.x;                           // 128 threads x float4
    float ds = g_dis[n];
    float w0 = ds * ds;
    float4 v = ((const float4*)(g_bufA + (size_t)n * Dd))[t];
    float4 acc;
    acc.x = v.x * w0; acc.y = v.y * w0; acc.z = v.z * w0; acc.w = v.w * w0;
    int e0 = g_off[n], e1 = g_off[n + 1];
    for (int e = e0; e < e1; e++) {
        int s = g_eidx[e];
        float w = g_ew[e];
        float4 u = ((const float4*)(g_bufA + (size_t)s * Dd))[t];
        acc.x += u.x * w; acc.y += u.y * w; acc.z += u.z * w; acc.w += u.w * w;
    }
    float4 b = ((const float4*)bias)[t];
    acc.x += b.x; acc.y += b.y; acc.z += b.z; acc.w += b.w;
    if (relu) {
        acc.x = fmaxf(acc.x, 0.0f); acc.y = fmaxf(acc.y, 0.0f);
        acc.z = fmaxf(acc.z, 0.0f); acc.w = fmaxf(acc.w, 0.0f);
    }
    if (writeSplit) {
        size_t o = (size_t)n * Dd + t * 4;
        float vs[4] = {acc.x, acc.y, acc.z, acc.w};
        __nv_bfloat16 hi[4], lo[4];
#pragma unroll
        for (int j = 0; j < 4; j++) {
            hi[j] = __float2bfloat16(vs[j]);
            lo[j] = __float2bfloat16(vs[j] - __bfloat162float(hi[j]));
        }
        *(uint2*)(g_Ahi + o) = *(uint2*)hi;
        *(uint2*)(g_Alo + o) = *(uint2*)lo;
    } else {
        ((float4*)(g_bufB + (size_t)n * Dd))[t] = acc;
    }
}

// ======== classifier + log_softmax: 16 nodes/block, 256 threads ========
__global__ void k_cls(const float* __restrict__ Wc, const float* __restrict__ bc,
                      float* __restrict__ logits, float* __restrict__ logp) {
    __shared__ float xs[16][Dd];
    int t = threadIdx.x;
    int n0 = blockIdx.x * 16;
    int c4 = (t & 15) * 4;
    int g  = t >> 4;

#pragma unroll
    for (int i = 0; i < 8; i++) {
        int slot = t + i * 256;
        int node = slot >> 7, qq = slot & 127;
        ((float4*)xs[node])[qq] = ((const float4*)(g_bufB + (size_t)(n0 + node) * Dd))[qq];
    }
    __syncthreads();

    float a0 = 0.f, a1 = 0.f, a2 = 0.f, a3 = 0.f;
    for (int k = 0; k < Dd; k += 4) {
        float4 xv = *(const float4*)&xs[g][k];
        float4 w0 = *(const float4*)(Wc + (size_t)k * Cc + c4);
        float4 w1 = *(const float4*)(Wc + (size_t)(k + 1) * Cc + c4);
        float4 w2 = *(const float4*)(Wc + (size_t)(k + 2) * Cc + c4);
        float4 w3 = *(const float4*)(Wc + (size_t)(k + 3) * Cc + c4);
        a0 += xv.x * w0.x + xv.y * w1.x + xv.z * w2.x + xv.w * w3.x;
        a1 += xv.x * w0.y + xv.y * w1.y + xv.z * w2.y + xv.w * w3.y;
        a2 += xv.x * w0.z + xv.y * w1.z + xv.z * w2.z + xv.w * w3.z;
        a3 += xv.x * w0.w + xv.y * w1.w + xv.z * w2.w + xv.w * w3.w;
    }
    float4 bv = *(const float4*)(bc + c4);
    a0 += bv.x; a1 += bv.y; a2 += bv.z; a3 += bv.w;

    int n = n0 + g;
    *(float4*)(logits + (size_t)n * Cc + c4) = make_float4(a0, a1, a2, a3);

    float mx = fmaxf(fmaxf(a0, a1), fmaxf(a2, a3));
#pragma unroll
    for (int m = 8; m > 0; m >>= 1)
        mx = fmaxf(mx, __shfl_xor_sync(0xffffffffu, mx, m, 16));
    float es = __expf(a0 - mx) + __expf(a1 - mx) + __expf(a2 - mx) + __expf(a3 - mx);
#pragma unroll
    for (int m = 8; m > 0; m >>= 1)
        es += __shfl_xor_sync(0xffffffffu, es, m, 16);
    float lse = mx + logf(es);
    *(float4*)(logp + (size_t)n * Cc + c4) =
        make_float4(a0 - lse, a1 - lse, a2 - lse, a3 - lse);
}

extern "C" void kernel_launch(void* const* d_in, const int* in_sizes, int n_in,
                              void* d_out, int out_size) {
    const float* x  = 0; const void* ei = 0;
    const float* W1 = 0; const float* b1 = 0;
    const float* W2 = 0; const float* b2 = 0;
    const float* Wc = 0; const float* bc = 0;
    for (int i = 0; i < n_in; i++) {
        int sz = in_sizes[i];
        if (sz == Nn * Dd)      { if (!x)  x  = (const float*)d_in[i]; }
        else if (sz == 2 * Ee)  { if (!ei) ei = d_in[i]; }
        else if (sz == Dd * Dd) { if (!W1) W1 = (const float*)d_in[i];
                                  else if (!W2) W2 = (const float*)d_in[i]; }
        else if (sz == Dd)      { if (!b1) b1 = (const float*)d_in[i];
                                  else if (!b2) b2 = (const float*)d_in[i]; }
        else if (sz == Dd * Cc) { if (!Wc) Wc = (const float*)d_in[i]; }
        else if (sz == Cc)      { if (!bc) bc = (const float*)d_in[i]; }
    }

    float* out    = (float*)d_out;
    float* logits = out;
    float* logp   = out + (out_size - Nn * Cc);

    static int smemSet = 0;
    if (!smemSet) {
        cudaFuncSetAttribute(k_gemm_mma,
                             cudaFuncAttributeMaxDynamicSharedMemorySize, 2 * STAGE_B);
        smemSet = 1;
    }

    k_detect_init<<<(Nn + 255) / 256, 256>>>((const int*)ei);
    k_count<<<(Ee + 255) / 256, 256>>>(ei);
    k_scan<<<1, 1024>>>();
    k_fill<<<(Ee + 255) / 256, 256>>>();
    k_splitW<<<(2 * Dd * Dd + 255) / 256, 256>>>(W1, W2);
    k_splitA<<<(Nn * Dd + 255) / 256, 256>>>(x);

    dim3 gemmGrid(Dd / 128, (Nn + 127) / 128);   // 4 x 79

    // ---- layer 1 ----
    k_gemm_mma<<<gemmGrid, 256, 2 * STAGE_B>>>(0);
    k_aggr<<<Nn, Dd / 4>>>(b1, 1, 1);            // writes bf16 hi/lo for layer 2

    // ---- layer 2 ----
    k_gemm_mma<<<gemmGrid, 256, 2 * STAGE_B>>>(1);
    k_aggr<<<Nn, Dd / 4>>>(b2, 0, 0);            // writes fp32 bufB for classifier

    // ---- classifier + log_softmax ----
    k_cls<<<Nn / 16, 256>>>(Wc, bc, logits, logp);
}